// round 13
// baseline (speedup 1.0000x reference)
#include <cuda_runtime.h>
#include <cuda_fp16.h>
#include <cstdint>

#define B_  32
#define T_  512
#define D_  2048
#define H_  128
#define G_  512
#define M_FWD (B_ * T_)

typedef unsigned long long ull;

__device__ float  g_xp[M_FWD * G_];       // forward gate preacts [B*T, 4H]
__device__ float  g_last[B_ * 2 * H_];    // [h_fwd | h_bwd]
__device__ float  g_gb[B_ * 384];         // backward gate preacts (i|g|o rows)
__device__ __half g_Ah[M_FWD * D_];       // fp16 copy of inputs
__device__ __half g_Wh[G_ * D_];          // fp16 copy of W_ih_f

extern __shared__ unsigned char dynsmem[];

// ---------------- helpers ---------------------------------------------------
__device__ __forceinline__ uint32_t smem_u32(const void* p) {
    uint32_t a;
    asm("{ .reg .u64 t; cvta.to.shared.u64 t, %1; cvt.u32.u64 %0, t; }"
        : "=r"(a) : "l"(p));
    return a;
}
// precise activations for single-use sites
__device__ __forceinline__ float fsig(float x)  { return 1.0f / (1.0f + expf(-x)); }
__device__ __forceinline__ float ftanh(float x) { return tanhf(x); }
// MUFU-EX2 activations for the recurrence (verified rel_err-neutral R11/R12)
__device__ __forceinline__ float esig(float x) {
    return __fdividef(1.0f, 1.0f + __expf(-x));
}
__device__ __forceinline__ float etanh(float x) {
    const float cx = fminf(fmaxf(x, -15.0f), 15.0f);
    const float e  = __expf(-2.0f * cx);
    return __fdividef(1.0f - e, 1.0f + e);
}
__device__ __forceinline__ uint32_t h2pack(float2 v) {
    __half2 h = __floats2half2_rn(v.x, v.y);
    return *(uint32_t*)&h;
}

#define SWZ128(o) ((o) ^ (((o) >> 3) & 0x70))

#define LDSM_X4(r0, r1, r2, r3, a) \
    asm volatile("ldmatrix.sync.aligned.m8n8.x4.shared.b16 {%0,%1,%2,%3}, [%4];" \
                 : "=r"(r0), "=r"(r1), "=r"(r2), "=r"(r3) : "r"(a))

#define MMA16816(d, a, b) \
    asm volatile("mma.sync.aligned.m16n8k16.row.col.f32.f16.f16.f32 " \
        "{%0,%1,%2,%3}, {%4,%5,%6,%7}, {%8,%9}, {%0,%1,%2,%3};" \
        : "+f"((d)[0]), "+f"((d)[1]), "+f"((d)[2]), "+f"((d)[3]) \
        : "r"((a)[0]), "r"((a)[1]), "r"((a)[2]), "r"((a)[3]), \
          "r"((b)[0]), "r"((b)[1]))

#define CP_ASYNC16(sa, gp) \
    asm volatile("cp.async.ca.shared.global [%0], [%1], 16;" \
                 :: "r"(sa), "l"(gp) : "memory")
#define CP_COMMIT()  asm volatile("cp.async.commit_group;" ::: "memory")
#define CP_WAIT(n)   asm volatile("cp.async.wait_group %0;" :: "n"(n) : "memory")

// ============================================================================
// fp32 -> fp16 convert
// ============================================================================
__global__ __launch_bounds__(256)
void cvt_fp16(const float* __restrict__ src, __half* __restrict__ dst, int n)
{
    const int i = (blockIdx.x * 256 + threadIdx.x) * 4;
    if (i < n) {
        const float4 v = *(const float4*)(src + i);
        *(__half2*)(dst + i)     = __floats2half2_rn(v.x, v.y);
        *(__half2*)(dst + i + 2) = __floats2half2_rn(v.z, v.w);
    }
}

// ============================================================================
// fp16 GEMM (unchanged: cp.async 3-stage + ldmatrix/mma, ~108 us)
// ============================================================================
#define GSTAGE 32768
#define GNIT   (D_ / 64)    // 32

__global__ __launch_bounds__(256)
void gemm_h(const __half* __restrict__ Ah, const __half* __restrict__ Wh,
            const float* __restrict__ bias0, const float* __restrict__ bias1,
            float* __restrict__ C)
{
    __shared__ float sb[128];
    char* sm = (char*)dynsmem;
    const uint32_t smu = smem_u32(sm);

    const int tid  = threadIdx.x;
    const int wid  = tid >> 5, lane = tid & 31;
    const int wm   = wid & 3,  wn   = wid >> 2;
    const int g    = lane >> 2, tg  = lane & 3;
    const int n0   = blockIdx.x * 128;
    const int m0   = blockIdx.y * 128;

    if (tid < 128) sb[tid] = bias0[n0 + tid] + bias1[n0 + tid];

    const int arow  = wm * 32 + (lane & 15);
    const int acsel = (lane & 16) ? 16 : 0;
    const int brow  = wn * 64 + (lane & 7) + ((lane & 16) ? 8 : 0);
    const int bcsel = (lane & 8) ? 16 : 0;

    const __half* Ab = Ah + (long)m0 * D_;
    const __half* Wb = Wh + (long)n0 * D_;

    const int sr0 = tid >> 3;
    const int sc8 = tid & 7;

    #define ISSUE_STAGE(s, kt) do {                                           \
        const uint32_t _st = smu + (s) * GSTAGE;                              \
        const long _k = (long)(kt) * 64;                                      \
        _Pragma("unroll")                                                     \
        for (int _i = 0; _i < 4; _i++) {                                      \
            const int _r = sr0 + _i * 32;                                     \
            const uint32_t _off = SWZ128(_r * 128 + sc8 * 16);                \
            CP_ASYNC16(_st + _off,         Ab + (long)_r * D_ + _k + sc8 * 8);\
            CP_ASYNC16(_st + 16384 + _off, Wb + (long)_r * D_ + _k + sc8 * 8);\
        }                                                                     \
    } while (0)

    ISSUE_STAGE(0, 0); CP_COMMIT();
    ISSUE_STAGE(1, 1); CP_COMMIT();

    float acc[2][8][4];
    #pragma unroll
    for (int i = 0; i < 2; i++)
        #pragma unroll
        for (int j = 0; j < 8; j++)
            #pragma unroll
            for (int r = 0; r < 4; r++) acc[i][j][r] = 0.0f;

    for (int it = 0; it < GNIT; it++) {
        if (it + 1 < GNIT) CP_WAIT(1); else CP_WAIT(0);
        __syncthreads();
        if (it + 2 < GNIT) { ISSUE_STAGE((it + 2) % 3, it + 2); CP_COMMIT(); }

        const uint32_t a_st = smu + (it % 3) * GSTAGE;
        const uint32_t b_st = a_st + 16384;
        #pragma unroll
        for (int kk = 0; kk < 4; kk++) {
            uint32_t af[2][4], bf[8][2];
            #pragma unroll
            for (int mf = 0; mf < 2; mf++) {
                const uint32_t off =
                    SWZ128((arow + mf * 16) * 128 + kk * 32 + acsel);
                LDSM_X4(af[mf][0], af[mf][1], af[mf][2], af[mf][3], a_st + off);
            }
            #pragma unroll
            for (int np = 0; np < 4; np++) {
                const uint32_t off =
                    SWZ128((brow + np * 16) * 128 + kk * 32 + bcsel);
                uint32_t r0, r1, r2, r3;
                LDSM_X4(r0, r1, r2, r3, b_st + off);
                bf[2 * np][0] = r0;     bf[2 * np][1] = r1;
                bf[2 * np + 1][0] = r2; bf[2 * np + 1][1] = r3;
            }
            #pragma unroll
            for (int mf = 0; mf < 2; mf++)
                #pragma unroll
                for (int nf = 0; nf < 8; nf++)
                    MMA16816(acc[mf][nf], af[mf], bf[nf]);
        }
    }

    #pragma unroll
    for (int mf = 0; mf < 2; mf++) {
        #pragma unroll
        for (int nf = 0; nf < 8; nf++) {
            const int cl  = wn * 64 + nf * 8 + 2 * tg;
            const float b0v = sb[cl], b1v = sb[cl + 1];
            const int r0 = m0 + wm * 32 + mf * 16 + g;
            float2 v0; v0.x = acc[mf][nf][0] + b0v; v0.y = acc[mf][nf][1] + b1v;
            *(float2*)(C + (long)r0 * G_ + n0 + cl) = v0;
            float2 v1; v1.x = acc[mf][nf][2] + b0v; v1.y = acc[mf][nf][3] + b1v;
            *(float2*)(C + (long)(r0 + 8) * G_ + n0 + cl) = v1;
        }
    }
}

// ============================================================================
// Forward LSTM recurrence v8 — HMMA, shortened chains + pre-activated gates.
// One CTA/batch, 512 threads = 16 warps, warp w owns gate rows [32w, 32w+32).
// k=128 split into two 4-deep accumulator chains (a: ks 0-3, b: ks 4-7) per
// m-tile -> 4 interleaved independent HMMA chains. Gate type is warp-uniform
// (warps 8-11 = g-gate = tanh; others sigmoid), so the tg==0 owner lanes
// apply the activation BEFORE the store: the 128-thread tail is just
// c = af*c + ai*ag; h = ao*etanh(c).
// ============================================================================
__global__ __launch_bounds__(512)
void lstm_hmma(const float* __restrict__ xp, const float* __restrict__ Whh,
               float* __restrict__ last)
{
    __shared__ __align__(16) __half h16[128];
    __shared__ float gate_s[512];

    const int tid = threadIdx.x, b = blockIdx.x;
    const int wid = tid >> 5, lane = tid & 31;
    const int g   = lane >> 2, tg = lane & 3;
    const int r0  = wid * 32 + g;
    const bool gw = (wid >= 8) && (wid < 12);   // tanh (g-gate) warps

    // ---- preload W_hh into a-fragments (once; fp32->fp16 on load) ----
    uint32_t af[2][8][4];
    #pragma unroll
    for (int m = 0; m < 2; m++) {
        const float* wr0 = Whh + (r0 + 16 * m) * 128;
        const float* wr1 = wr0 + 8 * 128;
        #pragma unroll
        for (int ks = 0; ks < 8; ks++) {
            af[m][ks][0] = h2pack(*(const float2*)(wr0 + 16 * ks + 2 * tg));
            af[m][ks][1] = h2pack(*(const float2*)(wr1 + 16 * ks + 2 * tg));
            af[m][ks][2] = h2pack(*(const float2*)(wr0 + 16 * ks + 8 + 2 * tg));
            af[m][ks][3] = h2pack(*(const float2*)(wr1 + 16 * ks + 8 + 2 * tg));
        }
    }
    if (tid < 128) h16[tid] = __float2half_rn(0.0f);
    float c = 0.0f;
    __syncthreads();

    const float* xpb = xp + (long)b * T_ * G_;
    float xv[2][2];
    #pragma unroll
    for (int m = 0; m < 2; m++) {
        xv[m][0] = xpb[r0 + 16 * m];
        xv[m][1] = xpb[r0 + 16 * m + 8];
    }

    for (int t = 0; t < T_; t++) {
        // hoist all b-fragment loads (independent; issue right after wake-up)
        uint32_t bf[8][2];
        #pragma unroll
        for (int ks = 0; ks < 8; ks++) {
            bf[ks][0] = *(const uint32_t*)(h16 + 16 * ks + 2 * tg);
            bf[ks][1] = *(const uint32_t*)(h16 + 16 * ks + 8 + 2 * tg);
        }
        // 4 independent 4-deep HMMA chains
        float a0a[4] = { xv[0][0], xv[0][0], xv[0][1], xv[0][1] };
        float a1a[4] = { xv[1][0], xv[1][0], xv[1][1], xv[1][1] };
        float a0b[4] = { 0.f, 0.f, 0.f, 0.f };
        float a1b[4] = { 0.f, 0.f, 0.f, 0.f };
        #pragma unroll
        for (int ks = 0; ks < 4; ks++) {
            MMA16816(a0a, af[0][ks],     bf[ks]);
            MMA16816(a1a, af[1][ks],     bf[ks]);
            MMA16816(a0b, af[0][ks + 4], bf[ks + 4]);
            MMA16816(a1b, af[1][ks + 4], bf[ks + 4]);
        }
        if (t + 1 < T_) {                        // prefetch next xp
            const float* nx = xpb + (long)(t + 1) * G_;
            #pragma unroll
            for (int m = 0; m < 2; m++) {
                xv[m][0] = nx[r0 + 16 * m];
                xv[m][1] = nx[r0 + 16 * m + 8];
            }
        }
        if (tg == 0) {                           // pre-activated gate store
            const float g0 = a0a[0] + a0b[0];
            const float g1 = a0a[2] + a0b[2];
            const float g2 = a1a[0] + a1b[0];
            const float g3 = a1a[2] + a1b[2];
            gate_s[r0]      = gw ? etanh(g0) : esig(g0);
            gate_s[r0 + 8]  = gw ? etanh(g1) : esig(g1);
            gate_s[r0 + 16] = gw ? etanh(g2) : esig(g2);
            gate_s[r0 + 24] = gw ? etanh(g3) : esig(g3);
        }
        __syncthreads();
        if (tid < 128) {
            const float ai = gate_s[tid],       afv = gate_s[128 + tid];
            const float ag = gate_s[256 + tid], ao  = gate_s[384 + tid];
            c = afv * c + ai * ag;
            const float h = ao * etanh(c);
            h16[tid] = __float2half_rn(h);
            if (t == T_ - 1) last[b * (2 * H_) + tid] = h;
        }
        __syncthreads();
    }
}

// ============================================================================
// Backward direction (unchanged): one step from zero state, 128 CTAs.
// ============================================================================
__global__ __launch_bounds__(1024)
void bwd_gemm(const float* __restrict__ x, const float* __restrict__ Wihb,
              const float* __restrict__ bihb, const float* __restrict__ bhhb,
              float* __restrict__ gb)
{
    __shared__ float xs[2048];
    const int b = blockIdx.y, slice = blockIdx.x;
    const int tid = threadIdx.x, warp = tid >> 5, lane = tid & 31;

    const float* xr = x + ((long)b * T_ + (T_ - 1)) * D_;
    for (int i = tid; i < 2048; i += 1024) xs[i] = xr[i];
    __syncthreads();

    #pragma unroll
    for (int jj = 0; jj < 3; jj++) {
        const int j = slice * 96 + warp * 3 + jj;     // 0..383
        const int r = (j < 128) ? j : (j + 128);      // skip f rows
        const float4* wr = (const float4*)(Wihb + (long)r * D_);
        float s = 0.0f;
        #pragma unroll
        for (int it = 0; it < 16; it++) {
            const float4 wv = wr[it * 32 + lane];
            const float4 hx = *(const float4*)(xs + 4 * (it * 32 + lane));
            s += wv.x * hx.x + wv.y * hx.y + wv.z * hx.z + wv.w * hx.w;
        }
        #pragma unroll
        for (int d = 16; d > 0; d >>= 1)
            s += __shfl_xor_sync(0xFFFFFFFFu, s, d);
        if (lane == 0) gb[b * 384 + j] = s + bihb[r] + bhhb[r];
    }
}

__global__ void bwd_point(const float* __restrict__ gb, float* __restrict__ last)
{
    const int b = blockIdx.x, j = threadIdx.x;   // 32 x 128
    const float* r = gb + b * 384;
    const float ci = fsig(r[j]) * ftanh(r[128 + j]);
    last[b * (2 * H_) + H_ + j] = fsig(r[256 + j]) * ftanh(ci);
}

// ============================================================================
// MLP head + softmax.
// ============================================================================
__global__ void head_kernel(const float* __restrict__ last,
                            const float* __restrict__ W1, const float* __restrict__ b1,
                            const float* __restrict__ W2, const float* __restrict__ b2,
                            const float* __restrict__ W3, const float* __restrict__ b3,
                            float* __restrict__ out)
{
    __shared__ float v[256], u[256], w2s[64], lg[11];
    const int b = blockIdx.x, tid = threadIdx.x;

    v[tid] = last[b * 256 + tid];
    __syncthreads();

    float a = b1[tid];
    #pragma unroll 8
    for (int k = 0; k < 256; k++) a = fmaf(W1[tid * 256 + k], v[k], a);
    u[tid] = a;
    __syncthreads();

    if (tid < 64) {
        float s = b2[tid];
        #pragma unroll 8
        for (int k = 0; k < 256; k++) s = fmaf(W2[tid * 256 + k], u[k], s);
        w2s[tid] = s;
    }
    __syncthreads();

    if (tid < 11) {
        float s = b3[tid];
        #pragma unroll
        for (int k = 0; k < 64; k++) s = fmaf(W3[tid * 64 + k], w2s[k], s);
        lg[tid] = s;
    }
    __syncthreads();

    if (tid == 0) {
        float mx = lg[0];
        for (int i = 1; i < 11; i++) mx = fmaxf(mx, lg[i]);
        float e[11], sum = 0.0f;
        for (int i = 0; i < 11; i++) { e[i] = expf(lg[i] - mx); sum += e[i]; }
        const float inv = 1.0f / sum;
        for (int i = 0; i < 11; i++) out[b * 11 + i] = e[i] * inv;
    }
}

// ============================================================================
extern "C" void kernel_launch(void* const* d_in, const int* in_sizes, int n_in,
                              void* d_out, int out_size)
{
    const float* x    = (const float*)d_in[0];
    const float* Wihf = (const float*)d_in[1];
    const float* Whhf = (const float*)d_in[2];
    const float* bihf = (const float*)d_in[3];
    const float* bhhf = (const float*)d_in[4];
    const float* Wihb = (const float*)d_in[5];
    const float* bihb = (const float*)d_in[7];
    const float* bhhb = (const float*)d_in[8];
    const float* W1 = (const float*)d_in[9];   const float* b1 = (const float*)d_in[10];
    const float* W2 = (const float*)d_in[11];  const float* b2 = (const float*)d_in[12];
    const float* W3 = (const float*)d_in[13];  const float* b3 = (const float*)d_in[14];
    float* out = (float*)d_out;

    void* p;
    cudaGetSymbolAddress(&p, g_xp);   float*  xp   = (float*)p;
    cudaGetSymbolAddress(&p, g_last); float*  last = (float*)p;
    cudaGetSymbolAddress(&p, g_gb);   float*  gb   = (float*)p;
    cudaGetSymbolAddress(&p, g_Ah);   __half* Ah   = (__half*)p;
    cudaGetSymbolAddress(&p, g_Wh);   __half* Wh   = (__half*)p;

    const int gemm_smem = 3 * GSTAGE;   // 96 KB
    cudaFuncSetAttribute(gemm_h, cudaFuncAttributeMaxDynamicSharedMemorySize, gemm_smem);

    // lstm at index 3 == the ncu-profiled slot (confirmed R1/R8-R12)
    cvt_fp16<<<(M_FWD * D_) / 1024, 256>>>(x,    Ah, M_FWD * D_);          // 0
    cvt_fp16<<<(G_ * D_) / 1024,    256>>>(Wihf, Wh, G_ * D_);             // 1
    gemm_h<<<dim3(G_ / 128, M_FWD / 128), 256, gemm_smem>>>(Ah, Wh, bihf, bhhf, xp); // 2
    lstm_hmma<<<B_, 512>>>(xp, Whhf, last);                                // 3
    bwd_gemm<<<dim3(4, B_), 1024>>>(x, Wihb, bihb, bhhb, gb);              // 4
    bwd_point<<<B_, 128>>>(gb, last);                                      // 5
    head_kernel<<<B_, 256>>>(last, W1, b1, W2, b2, W3, b3, out);           // 6
}

// round 14
// speedup vs baseline: 1.2343x; 1.2343x over previous
#include <cuda_runtime.h>
#include <cuda_fp16.h>
#include <cstdint>

#define B_  32
#define T_  512
#define D_  2048
#define H_  128
#define G_  512
#define M_FWD (B_ * T_)

typedef unsigned long long ull;

__device__ float  g_xp[M_FWD * G_];       // forward gate preacts [B*T, 4H]
__device__ float  g_last[B_ * 2 * H_];    // [h_fwd | h_bwd]
__device__ float  g_gb[B_ * 384];         // backward gate preacts (i|g|o rows)
__device__ __half g_Ah[M_FWD * D_];       // fp16 copy of inputs
__device__ __half g_Wh[G_ * D_];          // fp16 copy of W_ih_f

extern __shared__ unsigned char dynsmem[];

// ---------------- helpers ---------------------------------------------------
__device__ __forceinline__ uint32_t smem_u32(const void* p) {
    uint32_t a;
    asm("{ .reg .u64 t; cvta.to.shared.u64 t, %1; cvt.u32.u64 %0, t; }"
        : "=r"(a) : "l"(p));
    return a;
}
// precise activations for single-use sites
__device__ __forceinline__ float fsig(float x)  { return 1.0f / (1.0f + expf(-x)); }
__device__ __forceinline__ float ftanh(float x) { return tanhf(x); }
// MUFU-EX2 activations for the recurrence (verified rel_err-neutral R11/R12)
__device__ __forceinline__ float esig(float x) {
    return __fdividef(1.0f, 1.0f + __expf(-x));
}
__device__ __forceinline__ float etanh(float x) {
    const float cx = fminf(fmaxf(x, -15.0f), 15.0f);
    const float e  = __expf(-2.0f * cx);
    return __fdividef(1.0f - e, 1.0f + e);
}
__device__ __forceinline__ uint32_t h2pack(float2 v) {
    __half2 h = __floats2half2_rn(v.x, v.y);
    return *(uint32_t*)&h;
}

#define SWZ128(o) ((o) ^ (((o) >> 3) & 0x70))

#define LDSM_X4(r0, r1, r2, r3, a) \
    asm volatile("ldmatrix.sync.aligned.m8n8.x4.shared.b16 {%0,%1,%2,%3}, [%4];" \
                 : "=r"(r0), "=r"(r1), "=r"(r2), "=r"(r3) : "r"(a))

#define MMA16816(d, a, b) \
    asm volatile("mma.sync.aligned.m16n8k16.row.col.f32.f16.f16.f32 " \
        "{%0,%1,%2,%3}, {%4,%5,%6,%7}, {%8,%9}, {%0,%1,%2,%3};" \
        : "+f"((d)[0]), "+f"((d)[1]), "+f"((d)[2]), "+f"((d)[3]) \
        : "r"((a)[0]), "r"((a)[1]), "r"((a)[2]), "r"((a)[3]), \
          "r"((b)[0]), "r"((b)[1]))

#define CP_ASYNC16(sa, gp) \
    asm volatile("cp.async.ca.shared.global [%0], [%1], 16;" \
                 :: "r"(sa), "l"(gp) : "memory")
#define CP_COMMIT()  asm volatile("cp.async.commit_group;" ::: "memory")
#define CP_WAIT(n)   asm volatile("cp.async.wait_group %0;" :: "n"(n) : "memory")

// ============================================================================
// fp32 -> fp16 convert
// ============================================================================
__global__ __launch_bounds__(256)
void cvt_fp16(const float* __restrict__ src, __half* __restrict__ dst, int n)
{
    const int i = (blockIdx.x * 256 + threadIdx.x) * 4;
    if (i < n) {
        const float4 v = *(const float4*)(src + i);
        *(__half2*)(dst + i)     = __floats2half2_rn(v.x, v.y);
        *(__half2*)(dst + i + 2) = __floats2half2_rn(v.z, v.w);
    }
}

// ============================================================================
// fp16 GEMM (unchanged: cp.async 3-stage + ldmatrix/mma, ~108 us)
// ============================================================================
#define GSTAGE 32768
#define GNIT   (D_ / 64)    // 32

__global__ __launch_bounds__(256)
void gemm_h(const __half* __restrict__ Ah, const __half* __restrict__ Wh,
            const float* __restrict__ bias0, const float* __restrict__ bias1,
            float* __restrict__ C)
{
    __shared__ float sb[128];
    char* sm = (char*)dynsmem;
    const uint32_t smu = smem_u32(sm);

    const int tid  = threadIdx.x;
    const int wid  = tid >> 5, lane = tid & 31;
    const int wm   = wid & 3,  wn   = wid >> 2;
    const int g    = lane >> 2, tg  = lane & 3;
    const int n0   = blockIdx.x * 128;
    const int m0   = blockIdx.y * 128;

    if (tid < 128) sb[tid] = bias0[n0 + tid] + bias1[n0 + tid];

    const int arow  = wm * 32 + (lane & 15);
    const int acsel = (lane & 16) ? 16 : 0;
    const int brow  = wn * 64 + (lane & 7) + ((lane & 16) ? 8 : 0);
    const int bcsel = (lane & 8) ? 16 : 0;

    const __half* Ab = Ah + (long)m0 * D_;
    const __half* Wb = Wh + (long)n0 * D_;

    const int sr0 = tid >> 3;
    const int sc8 = tid & 7;

    #define ISSUE_STAGE(s, kt) do {                                           \
        const uint32_t _st = smu + (s) * GSTAGE;                              \
        const long _k = (long)(kt) * 64;                                      \
        _Pragma("unroll")                                                     \
        for (int _i = 0; _i < 4; _i++) {                                      \
            const int _r = sr0 + _i * 32;                                     \
            const uint32_t _off = SWZ128(_r * 128 + sc8 * 16);                \
            CP_ASYNC16(_st + _off,         Ab + (long)_r * D_ + _k + sc8 * 8);\
            CP_ASYNC16(_st + 16384 + _off, Wb + (long)_r * D_ + _k + sc8 * 8);\
        }                                                                     \
    } while (0)

    ISSUE_STAGE(0, 0); CP_COMMIT();
    ISSUE_STAGE(1, 1); CP_COMMIT();

    float acc[2][8][4];
    #pragma unroll
    for (int i = 0; i < 2; i++)
        #pragma unroll
        for (int j = 0; j < 8; j++)
            #pragma unroll
            for (int r = 0; r < 4; r++) acc[i][j][r] = 0.0f;

    for (int it = 0; it < GNIT; it++) {
        if (it + 1 < GNIT) CP_WAIT(1); else CP_WAIT(0);
        __syncthreads();
        if (it + 2 < GNIT) { ISSUE_STAGE((it + 2) % 3, it + 2); CP_COMMIT(); }

        const uint32_t a_st = smu + (it % 3) * GSTAGE;
        const uint32_t b_st = a_st + 16384;
        #pragma unroll
        for (int kk = 0; kk < 4; kk++) {
            uint32_t af[2][4], bf[8][2];
            #pragma unroll
            for (int mf = 0; mf < 2; mf++) {
                const uint32_t off =
                    SWZ128((arow + mf * 16) * 128 + kk * 32 + acsel);
                LDSM_X4(af[mf][0], af[mf][1], af[mf][2], af[mf][3], a_st + off);
            }
            #pragma unroll
            for (int np = 0; np < 4; np++) {
                const uint32_t off =
                    SWZ128((brow + np * 16) * 128 + kk * 32 + bcsel);
                uint32_t r0, r1, r2, r3;
                LDSM_X4(r0, r1, r2, r3, b_st + off);
                bf[2 * np][0] = r0;     bf[2 * np][1] = r1;
                bf[2 * np + 1][0] = r2; bf[2 * np + 1][1] = r3;
            }
            #pragma unroll
            for (int mf = 0; mf < 2; mf++)
                #pragma unroll
                for (int nf = 0; nf < 8; nf++)
                    MMA16816(acc[mf][nf], af[mf], bf[nf]);
        }
    }

    #pragma unroll
    for (int mf = 0; mf < 2; mf++) {
        #pragma unroll
        for (int nf = 0; nf < 8; nf++) {
            const int cl  = wn * 64 + nf * 8 + 2 * tg;
            const float b0v = sb[cl], b1v = sb[cl + 1];
            const int r0 = m0 + wm * 32 + mf * 16 + g;
            float2 v0; v0.x = acc[mf][nf][0] + b0v; v0.y = acc[mf][nf][1] + b1v;
            *(float2*)(C + (long)r0 * G_ + n0 + cl) = v0;
            float2 v1; v1.x = acc[mf][nf][2] + b0v; v1.y = acc[mf][nf][3] + b1v;
            *(float2*)(C + (long)(r0 + 8) * G_ + n0 + cl) = v1;
        }
    }
}

// ============================================================================
// Forward LSTM recurrence v9 — R12 structure (307 us, best known) with ONE
// change: h stored in smem in a PERMUTED fp16 layout so each lane fetches its
// two b-fragments of a ks-block with a single LDS.64 instead of two LDS.32.
// Permutation: for h-row j (j = 16*ks + r):
//   r < 8:  pos = 16*ks + (r>>1)*4 + (r&1)         (b0 halves: k=2tg, 2tg+1)
//   r >= 8: pos = 16*ks + ((r-8)>>1)*4 + 2 + (r&1) (b1 halves: k=2tg+8, +9)
// Lane (ks, tg) then reads the 8-byte group at half-offset 16*ks + 4*tg.
// Everything else is byte-identical to R12's lstm_hmma.
// ============================================================================
__global__ __launch_bounds__(512)
void lstm_hmma(const float* __restrict__ xp, const float* __restrict__ Whh,
               float* __restrict__ last)
{
    __shared__ __align__(16) __half h16[128];   // permuted layout
    __shared__ float gate_s[512];

    const int tid = threadIdx.x, b = blockIdx.x;
    const int wid = tid >> 5, lane = tid & 31;
    const int g   = lane >> 2, tg = lane & 3;
    const int r0  = wid * 32 + g;

    // ---- preload W_hh into a-fragments (once; fp32->fp16 on load) ----
    uint32_t af[2][8][4];
    #pragma unroll
    for (int m = 0; m < 2; m++) {
        const float* wr0 = Whh + (r0 + 16 * m) * 128;
        const float* wr1 = wr0 + 8 * 128;
        #pragma unroll
        for (int ks = 0; ks < 8; ks++) {
            af[m][ks][0] = h2pack(*(const float2*)(wr0 + 16 * ks + 2 * tg));
            af[m][ks][1] = h2pack(*(const float2*)(wr1 + 16 * ks + 2 * tg));
            af[m][ks][2] = h2pack(*(const float2*)(wr0 + 16 * ks + 8 + 2 * tg));
            af[m][ks][3] = h2pack(*(const float2*)(wr1 + 16 * ks + 8 + 2 * tg));
        }
    }
    if (tid < 128) h16[tid] = __float2half_rn(0.0f);
    float c = 0.0f;

    // permuted write position for this thread's h-row (tail threads only)
    __half* hw = h16;
    if (tid < 128) {
        const int r = tid & 15;
        const int pos = (tid & ~15)
                      + ((r < 8) ? ((r >> 1) * 4 + (r & 1))
                                 : (((r - 8) >> 1) * 4 + 2 + (r & 1)));
        hw = h16 + pos;
    }
    __syncthreads();

    const float* xpb = xp + (long)b * T_ * G_;
    float xv[2][2];
    #pragma unroll
    for (int m = 0; m < 2; m++) {
        xv[m][0] = xpb[r0 + 16 * m];
        xv[m][1] = xpb[r0 + 16 * m + 8];
    }

    const char* hrd = (const char*)h16 + tg * 8;   // lane's LDS.64 base

    for (int t = 0; t < T_; t++) {
        float acc0[4] = { xv[0][0], xv[0][0], xv[0][1], xv[0][1] };
        float acc1[4] = { xv[1][0], xv[1][0], xv[1][1], xv[1][1] };
        #pragma unroll
        for (int ks = 0; ks < 8; ks++) {
            const ull hv = *(const ull*)(hrd + ks * 32);   // one LDS.64
            uint32_t bf[2];
            bf[0] = (uint32_t)hv;           // k = 2tg, 2tg+1
            bf[1] = (uint32_t)(hv >> 32);   // k = 2tg+8, 2tg+9
            MMA16816(acc0, af[0][ks], bf);
            MMA16816(acc1, af[1][ks], bf);
        }
        if (t + 1 < T_) {                        // prefetch next xp
            const float* nx = xpb + (long)(t + 1) * G_;
            #pragma unroll
            for (int m = 0; m < 2; m++) {
                xv[m][0] = nx[r0 + 16 * m];
                xv[m][1] = nx[r0 + 16 * m + 8];
            }
        }
        if (tg == 0) {                            // all acc cols identical
            gate_s[r0]      = acc0[0];
            gate_s[r0 + 8]  = acc0[2];
            gate_s[r0 + 16] = acc1[0];
            gate_s[r0 + 24] = acc1[2];
        }
        __syncthreads();
        if (tid < 128) {
            const float gi = gate_s[tid],       gf = gate_s[128 + tid];
            const float gg = gate_s[256 + tid], go = gate_s[384 + tid];
            c = esig(gf) * c + esig(gi) * etanh(gg);
            const float h = esig(go) * etanh(c);
            *hw = __float2half_rn(h);
            if (t == T_ - 1) last[b * (2 * H_) + tid] = h;
        }
        __syncthreads();
    }
}

// ============================================================================
// Backward direction (unchanged): one step from zero state, 128 CTAs.
// ============================================================================
__global__ __launch_bounds__(1024)
void bwd_gemm(const float* __restrict__ x, const float* __restrict__ Wihb,
              const float* __restrict__ bihb, const float* __restrict__ bhhb,
              float* __restrict__ gb)
{
    __shared__ float xs[2048];
    const int b = blockIdx.y, slice = blockIdx.x;
    const int tid = threadIdx.x, warp = tid >> 5, lane = tid & 31;

    const float* xr = x + ((long)b * T_ + (T_ - 1)) * D_;
    for (int i = tid; i < 2048; i += 1024) xs[i] = xr[i];
    __syncthreads();

    #pragma unroll
    for (int jj = 0; jj < 3; jj++) {
        const int j = slice * 96 + warp * 3 + jj;     // 0..383
        const int r = (j < 128) ? j : (j + 128);      // skip f rows
        const float4* wr = (const float4*)(Wihb + (long)r * D_);
        float s = 0.0f;
        #pragma unroll
        for (int it = 0; it < 16; it++) {
            const float4 wv = wr[it * 32 + lane];
            const float4 hx = *(const float4*)(xs + 4 * (it * 32 + lane));
            s += wv.x * hx.x + wv.y * hx.y + wv.z * hx.z + wv.w * hx.w;
        }
        #pragma unroll
        for (int d = 16; d > 0; d >>= 1)
            s += __shfl_xor_sync(0xFFFFFFFFu, s, d);
        if (lane == 0) gb[b * 384 + j] = s + bihb[r] + bhhb[r];
    }
}

__global__ void bwd_point(const float* __restrict__ gb, float* __restrict__ last)
{
    const int b = blockIdx.x, j = threadIdx.x;   // 32 x 128
    const float* r = gb + b * 384;
    const float ci = fsig(r[j]) * ftanh(r[128 + j]);
    last[b * (2 * H_) + H_ + j] = fsig(r[256 + j]) * ftanh(ci);
}

// ============================================================================
// MLP head + softmax.
// ============================================================================
__global__ void head_kernel(const float* __restrict__ last,
                            const float* __restrict__ W1, const float* __restrict__ b1,
                            const float* __restrict__ W2, const float* __restrict__ b2,
                            const float* __restrict__ W3, const float* __restrict__ b3,
                            float* __restrict__ out)
{
    __shared__ float v[256], u[256], w2s[64], lg[11];
    const int b = blockIdx.x, tid = threadIdx.x;

    v[tid] = last[b * 256 + tid];
    __syncthreads();

    float a = b1[tid];
    #pragma unroll 8
    for (int k = 0; k < 256; k++) a = fmaf(W1[tid * 256 + k], v[k], a);
    u[tid] = a;
    __syncthreads();

    if (tid < 64) {
        float s = b2[tid];
        #pragma unroll 8
        for (int k = 0; k < 256; k++) s = fmaf(W2[tid * 256 + k], u[k], s);
        w2s[tid] = s;
    }
    __syncthreads();

    if (tid < 11) {
        float s = b3[tid];
        #pragma unroll
        for (int k = 0; k < 64; k++) s = fmaf(W3[tid * 64 + k], w2s[k], s);
        lg[tid] = s;
    }
    __syncthreads();

    if (tid == 0) {
        float mx = lg[0];
        for (int i = 1; i < 11; i++) mx = fmaxf(mx, lg[i]);
        float e[11], sum = 0.0f;
        for (int i = 0; i < 11; i++) { e[i] = expf(lg[i] - mx); sum += e[i]; }
        const float inv = 1.0f / sum;
        for (int i = 0; i < 11; i++) out[b * 11 + i] = e[i] * inv;
    }
}

// ============================================================================
extern "C" void kernel_launch(void* const* d_in, const int* in_sizes, int n_in,
                              void* d_out, int out_size)
{
    const float* x    = (const float*)d_in[0];
    const float* Wihf = (const float*)d_in[1];
    const float* Whhf = (const float*)d_in[2];
    const float* bihf = (const float*)d_in[3];
    const float* bhhf = (const float*)d_in[4];
    const float* Wihb = (const float*)d_in[5];
    const float* bihb = (const float*)d_in[7];
    const float* bhhb = (const float*)d_in[8];
    const float* W1 = (const float*)d_in[9];   const float* b1 = (const float*)d_in[10];
    const float* W2 = (const float*)d_in[11];  const float* b2 = (const float*)d_in[12];
    const float* W3 = (const float*)d_in[13];  const float* b3 = (const float*)d_in[14];
    float* out = (float*)d_out;

    void* p;
    cudaGetSymbolAddress(&p, g_xp);   float*  xp   = (float*)p;
    cudaGetSymbolAddress(&p, g_last); float*  last = (float*)p;
    cudaGetSymbolAddress(&p, g_gb);   float*  gb   = (float*)p;
    cudaGetSymbolAddress(&p, g_Ah);   __half* Ah   = (__half*)p;
    cudaGetSymbolAddress(&p, g_Wh);   __half* Wh   = (__half*)p;

    const int gemm_smem = 3 * GSTAGE;   // 96 KB
    cudaFuncSetAttribute(gemm_h, cudaFuncAttributeMaxDynamicSharedMemorySize, gemm_smem);

    // lstm at index 3 == the ncu-profiled slot (confirmed R1/R8-R13)
    cvt_fp16<<<(M_FWD * D_) / 1024, 256>>>(x,    Ah, M_FWD * D_);          // 0
    cvt_fp16<<<(G_ * D_) / 1024,    256>>>(Wihf, Wh, G_ * D_);             // 1
    gemm_h<<<dim3(G_ / 128, M_FWD / 128), 256, gemm_smem>>>(Ah, Wh, bihf, bhhf, xp); // 2
    lstm_hmma<<<B_, 512>>>(xp, Whhf, last);                                // 3
    bwd_gemm<<<dim3(4, B_), 1024>>>(x, Wihb, bihb, bhhb, gb);              // 4
    bwd_point<<<B_, 128>>>(gb, last);                                      // 5
    head_kernel<<<B_, 256>>>(last, W1, b1, W2, b2, W3, b3, out);           // 6
}

// round 15
// speedup vs baseline: 1.2581x; 1.0193x over previous
#include <cuda_runtime.h>
#include <cuda_fp16.h>
#include <cstdint>

#define B_  32
#define T_  512
#define D_  2048
#define H_  128
#define G_  512
#define M_FWD (B_ * T_)

typedef unsigned long long ull;

__device__ float  g_xp[M_FWD * G_];       // forward gate preacts [B*T, 4H]
__device__ float  g_last[B_ * 2 * H_];    // [h_fwd | h_bwd]
__device__ float  g_gb[B_ * 384];         // backward gate preacts (i|g|o rows)
__device__ __half g_Ah[M_FWD * D_];       // fp16 copy of inputs
__device__ __half g_Wh[G_ * D_];          // fp16 copy of W_ih_f

extern __shared__ unsigned char dynsmem[];

// ---------------- helpers ---------------------------------------------------
__device__ __forceinline__ uint32_t smem_u32(const void* p) {
    uint32_t a;
    asm("{ .reg .u64 t; cvta.to.shared.u64 t, %1; cvt.u32.u64 %0, t; }"
        : "=r"(a) : "l"(p));
    return a;
}
// precise activations for single-use sites
__device__ __forceinline__ float fsig(float x)  { return 1.0f / (1.0f + expf(-x)); }
__device__ __forceinline__ float ftanh(float x) { return tanhf(x); }
// MUFU-EX2 activations for the recurrence (verified rel_err-neutral R11-R14)
__device__ __forceinline__ float esig(float x) {
    return __fdividef(1.0f, 1.0f + __expf(-x));
}
__device__ __forceinline__ float etanh(float x) {
    const float cx = fminf(fmaxf(x, -15.0f), 15.0f);
    const float e  = __expf(-2.0f * cx);
    return __fdividef(1.0f - e, 1.0f + e);
}
__device__ __forceinline__ uint32_t h2pack(float2 v) {
    __half2 h = __floats2half2_rn(v.x, v.y);
    return *(uint32_t*)&h;
}

#define SWZ128(o) ((o) ^ (((o) >> 3) & 0x70))

#define LDSM_X4(r0, r1, r2, r3, a) \
    asm volatile("ldmatrix.sync.aligned.m8n8.x4.shared.b16 {%0,%1,%2,%3}, [%4];" \
                 : "=r"(r0), "=r"(r1), "=r"(r2), "=r"(r3) : "r"(a))

#define MMA16816(d, a, b) \
    asm volatile("mma.sync.aligned.m16n8k16.row.col.f32.f16.f16.f32 " \
        "{%0,%1,%2,%3}, {%4,%5,%6,%7}, {%8,%9}, {%0,%1,%2,%3};" \
        : "+f"((d)[0]), "+f"((d)[1]), "+f"((d)[2]), "+f"((d)[3]) \
        : "r"((a)[0]), "r"((a)[1]), "r"((a)[2]), "r"((a)[3]), \
          "r"((b)[0]), "r"((b)[1]))

#define CP_ASYNC16(sa, gp) \
    asm volatile("cp.async.ca.shared.global [%0], [%1], 16;" \
                 :: "r"(sa), "l"(gp) : "memory")
#define CP_COMMIT()  asm volatile("cp.async.commit_group;" ::: "memory")
#define CP_WAIT(n)   asm volatile("cp.async.wait_group %0;" :: "n"(n) : "memory")

// ============================================================================
// fp32 -> fp16 convert
// ============================================================================
__global__ __launch_bounds__(256)
void cvt_fp16(const float* __restrict__ src, __half* __restrict__ dst, int n)
{
    const int i = (blockIdx.x * 256 + threadIdx.x) * 4;
    if (i < n) {
        const float4 v = *(const float4*)(src + i);
        *(__half2*)(dst + i)     = __floats2half2_rn(v.x, v.y);
        *(__half2*)(dst + i + 2) = __floats2half2_rn(v.z, v.w);
    }
}

// ============================================================================
// fp16 GEMM (unchanged: cp.async 3-stage + ldmatrix/mma, ~108 us)
// ============================================================================
#define GSTAGE 32768
#define GNIT   (D_ / 64)    // 32

__global__ __launch_bounds__(256)
void gemm_h(const __half* __restrict__ Ah, const __half* __restrict__ Wh,
            const float* __restrict__ bias0, const float* __restrict__ bias1,
            float* __restrict__ C)
{
    __shared__ float sb[128];
    char* sm = (char*)dynsmem;
    const uint32_t smu = smem_u32(sm);

    const int tid  = threadIdx.x;
    const int wid  = tid >> 5, lane = tid & 31;
    const int wm   = wid & 3,  wn   = wid >> 2;
    const int g    = lane >> 2, tg  = lane & 3;
    const int n0   = blockIdx.x * 128;
    const int m0   = blockIdx.y * 128;

    if (tid < 128) sb[tid] = bias0[n0 + tid] + bias1[n0 + tid];

    const int arow  = wm * 32 + (lane & 15);
    const int acsel = (lane & 16) ? 16 : 0;
    const int brow  = wn * 64 + (lane & 7) + ((lane & 16) ? 8 : 0);
    const int bcsel = (lane & 8) ? 16 : 0;

    const __half* Ab = Ah + (long)m0 * D_;
    const __half* Wb = Wh + (long)n0 * D_;

    const int sr0 = tid >> 3;
    const int sc8 = tid & 7;

    #define ISSUE_STAGE(s, kt) do {                                           \
        const uint32_t _st = smu + (s) * GSTAGE;                              \
        const long _k = (long)(kt) * 64;                                      \
        _Pragma("unroll")                                                     \
        for (int _i = 0; _i < 4; _i++) {                                      \
            const int _r = sr0 + _i * 32;                                     \
            const uint32_t _off = SWZ128(_r * 128 + sc8 * 16);                \
            CP_ASYNC16(_st + _off,         Ab + (long)_r * D_ + _k + sc8 * 8);\
            CP_ASYNC16(_st + 16384 + _off, Wb + (long)_r * D_ + _k + sc8 * 8);\
        }                                                                     \
    } while (0)

    ISSUE_STAGE(0, 0); CP_COMMIT();
    ISSUE_STAGE(1, 1); CP_COMMIT();

    float acc[2][8][4];
    #pragma unroll
    for (int i = 0; i < 2; i++)
        #pragma unroll
        for (int j = 0; j < 8; j++)
            #pragma unroll
            for (int r = 0; r < 4; r++) acc[i][j][r] = 0.0f;

    for (int it = 0; it < GNIT; it++) {
        if (it + 1 < GNIT) CP_WAIT(1); else CP_WAIT(0);
        __syncthreads();
        if (it + 2 < GNIT) { ISSUE_STAGE((it + 2) % 3, it + 2); CP_COMMIT(); }

        const uint32_t a_st = smu + (it % 3) * GSTAGE;
        const uint32_t b_st = a_st + 16384;
        #pragma unroll
        for (int kk = 0; kk < 4; kk++) {
            uint32_t af[2][4], bf[8][2];
            #pragma unroll
            for (int mf = 0; mf < 2; mf++) {
                const uint32_t off =
                    SWZ128((arow + mf * 16) * 128 + kk * 32 + acsel);
                LDSM_X4(af[mf][0], af[mf][1], af[mf][2], af[mf][3], a_st + off);
            }
            #pragma unroll
            for (int np = 0; np < 4; np++) {
                const uint32_t off =
                    SWZ128((brow + np * 16) * 128 + kk * 32 + bcsel);
                uint32_t r0, r1, r2, r3;
                LDSM_X4(r0, r1, r2, r3, b_st + off);
                bf[2 * np][0] = r0;     bf[2 * np][1] = r1;
                bf[2 * np + 1][0] = r2; bf[2 * np + 1][1] = r3;
            }
            #pragma unroll
            for (int mf = 0; mf < 2; mf++)
                #pragma unroll
                for (int nf = 0; nf < 8; nf++)
                    MMA16816(acc[mf][nf], af[mf], bf[nf]);
        }
    }

    #pragma unroll
    for (int mf = 0; mf < 2; mf++) {
        #pragma unroll
        for (int nf = 0; nf < 8; nf++) {
            const int cl  = wn * 64 + nf * 8 + 2 * tg;
            const float b0v = sb[cl], b1v = sb[cl + 1];
            const int r0 = m0 + wm * 32 + mf * 16 + g;
            float2 v0; v0.x = acc[mf][nf][0] + b0v; v0.y = acc[mf][nf][1] + b1v;
            *(float2*)(C + (long)r0 * G_ + n0 + cl) = v0;
            float2 v1; v1.x = acc[mf][nf][2] + b0v; v1.y = acc[mf][nf][3] + b1v;
            *(float2*)(C + (long)(r0 + 8) * G_ + n0 + cl) = v1;
        }
    }
}

// ============================================================================
// Forward LSTM recurrence v10 — gate-fused HMMA, ONE barrier per step.
// Row->fragment permutation: lane (warp w, g) owns h-index j = 8w+g with
//   tile0: frag row g  = Whh[i_j],  frag row g+8 = Whh[f_j]
//   tile1: frag row g  = Whh[g_j],  frag row g+8 = Whh[o_j]
// All B columns carry the same h (validated R12/R14), so acc is tg-replicated:
//   acc0[0]=i, acc0[2]=f, acc1[0]=g, acc1[2]=o  -> full pointwise in-lane.
// h double-buffered in permuted fp16 layout (R14's LDS.64 read trick);
// single __syncthreads separates write(t) from read(t+1).
// ============================================================================
__global__ __launch_bounds__(512)
void lstm_hmma(const float* __restrict__ xp, const float* __restrict__ Whh,
               float* __restrict__ last)
{
    __shared__ __align__(16) __half h16[2][128];

    const int tid = threadIdx.x, b = blockIdx.x;
    const int wid = tid >> 5, lane = tid & 31;
    const int g   = lane >> 2, tg = lane & 3;
    const int j   = wid * 8 + g;          // h-index owned by this lane

    const int ri = j, rf = 128 + j, rg = 256 + j, ro = 384 + j;

    // ---- preload permuted W_hh a-fragments (once; fp32->fp16 on load) ----
    uint32_t af[2][8][4];
    #pragma unroll
    for (int ks = 0; ks < 8; ks++) {
        const float* pi = Whh + ri * 128 + 16 * ks + 2 * tg;
        const float* pf = Whh + rf * 128 + 16 * ks + 2 * tg;
        const float* pg = Whh + rg * 128 + 16 * ks + 2 * tg;
        const float* po = Whh + ro * 128 + 16 * ks + 2 * tg;
        af[0][ks][0] = h2pack(*(const float2*)pi);
        af[0][ks][1] = h2pack(*(const float2*)pf);
        af[0][ks][2] = h2pack(*(const float2*)(pi + 8));
        af[0][ks][3] = h2pack(*(const float2*)(pf + 8));
        af[1][ks][0] = h2pack(*(const float2*)pg);
        af[1][ks][1] = h2pack(*(const float2*)po);
        af[1][ks][2] = h2pack(*(const float2*)(pg + 8));
        af[1][ks][3] = h2pack(*(const float2*)(po + 8));
    }
    if (tid < 128) {
        h16[0][tid] = __float2half_rn(0.0f);
        h16[1][tid] = __float2half_rn(0.0f);
    }
    // permuted write position for h-row j (same permutation as the reader)
    int pos;
    {
        const int r = j & 15;
        pos = (j & ~15) + ((r < 8) ? ((r >> 1) * 4 + (r & 1))
                                   : (((r - 8) >> 1) * 4 + 2 + (r & 1)));
    }
    float c = 0.0f;
    __syncthreads();

    const float* xpb = xp + (long)b * T_ * G_;
    float xi = xpb[ri], xf = xpb[rf], xg = xpb[rg], xo = xpb[ro];

    for (int t = 0; t < T_; t++) {
        const char* hrd = (const char*)h16[t & 1] + tg * 8;
        float acc0[4] = { 0.f, 0.f, 0.f, 0.f };
        float acc1[4] = { 0.f, 0.f, 0.f, 0.f };
        #pragma unroll
        for (int ks = 0; ks < 8; ks++) {
            const ull hv = *(const ull*)(hrd + ks * 32);   // one LDS.64
            uint32_t bf[2];
            bf[0] = (uint32_t)hv;           // k = 2tg, 2tg+1
            bf[1] = (uint32_t)(hv >> 32);   // k = 2tg+8, 2tg+9
            MMA16816(acc0, af[0][ks], bf);
            MMA16816(acc1, af[1][ks], bf);
        }
        const float gi = acc0[0] + xi;
        const float gf = acc0[2] + xf;
        const float gg = acc1[0] + xg;
        const float go = acc1[2] + xo;
        if (t + 1 < T_) {                        // prefetch next xp
            const float* nx = xpb + (long)(t + 1) * G_;
            xi = nx[ri]; xf = nx[rf]; xg = nx[rg]; xo = nx[ro];
        }
        // full pointwise in-lane (replicated across tg; deterministic)
        c = esig(gf) * c + esig(gi) * etanh(gg);
        const float h = esig(go) * etanh(c);
        if (tg == 0) {
            h16[(t + 1) & 1][pos] = __float2half_rn(h);
            if (t == T_ - 1) last[b * (2 * H_) + j] = h;
        }
        __syncthreads();                          // write(t) -> read(t+1)
    }
}

// ============================================================================
// Backward direction (unchanged): one step from zero state, 128 CTAs.
// ============================================================================
__global__ __launch_bounds__(1024)
void bwd_gemm(const float* __restrict__ x, const float* __restrict__ Wihb,
              const float* __restrict__ bihb, const float* __restrict__ bhhb,
              float* __restrict__ gb)
{
    __shared__ float xs[2048];
    const int b = blockIdx.y, slice = blockIdx.x;
    const int tid = threadIdx.x, warp = tid >> 5, lane = tid & 31;

    const float* xr = x + ((long)b * T_ + (T_ - 1)) * D_;
    for (int i = tid; i < 2048; i += 1024) xs[i] = xr[i];
    __syncthreads();

    #pragma unroll
    for (int jj = 0; jj < 3; jj++) {
        const int j = slice * 96 + warp * 3 + jj;     // 0..383
        const int r = (j < 128) ? j : (j + 128);      // skip f rows
        const float4* wr = (const float4*)(Wihb + (long)r * D_);
        float s = 0.0f;
        #pragma unroll
        for (int it = 0; it < 16; it++) {
            const float4 wv = wr[it * 32 + lane];
            const float4 hx = *(const float4*)(xs + 4 * (it * 32 + lane));
            s += wv.x * hx.x + wv.y * hx.y + wv.z * hx.z + wv.w * hx.w;
        }
        #pragma unroll
        for (int d = 16; d > 0; d >>= 1)
            s += __shfl_xor_sync(0xFFFFFFFFu, s, d);
        if (lane == 0) gb[b * 384 + j] = s + bihb[r] + bhhb[r];
    }
}

__global__ void bwd_point(const float* __restrict__ gb, float* __restrict__ last)
{
    const int b = blockIdx.x, j = threadIdx.x;   // 32 x 128
    const float* r = gb + b * 384;
    const float ci = fsig(r[j]) * ftanh(r[128 + j]);
    last[b * (2 * H_) + H_ + j] = fsig(r[256 + j]) * ftanh(ci);
}

// ============================================================================
// MLP head + softmax.
// ============================================================================
__global__ void head_kernel(const float* __restrict__ last,
                            const float* __restrict__ W1, const float* __restrict__ b1,
                            const float* __restrict__ W2, const float* __restrict__ b2,
                            const float* __restrict__ W3, const float* __restrict__ b3,
                            float* __restrict__ out)
{
    __shared__ float v[256], u[256], w2s[64], lg[11];
    const int b = blockIdx.x, tid = threadIdx.x;

    v[tid] = last[b * 256 + tid];
    __syncthreads();

    float a = b1[tid];
    #pragma unroll 8
    for (int k = 0; k < 256; k++) a = fmaf(W1[tid * 256 + k], v[k], a);
    u[tid] = a;
    __syncthreads();

    if (tid < 64) {
        float s = b2[tid];
        #pragma unroll 8
        for (int k = 0; k < 256; k++) s = fmaf(W2[tid * 256 + k], u[k], s);
        w2s[tid] = s;
    }
    __syncthreads();

    if (tid < 11) {
        float s = b3[tid];
        #pragma unroll
        for (int k = 0; k < 64; k++) s = fmaf(W3[tid * 64 + k], w2s[k], s);
        lg[tid] = s;
    }
    __syncthreads();

    if (tid == 0) {
        float mx = lg[0];
        for (int i = 1; i < 11; i++) mx = fmaxf(mx, lg[i]);
        float e[11], sum = 0.0f;
        for (int i = 0; i < 11; i++) { e[i] = expf(lg[i] - mx); sum += e[i]; }
        const float inv = 1.0f / sum;
        for (int i = 0; i < 11; i++) out[b * 11 + i] = e[i] * inv;
    }
}

// ============================================================================
extern "C" void kernel_launch(void* const* d_in, const int* in_sizes, int n_in,
                              void* d_out, int out_size)
{
    const float* x    = (const float*)d_in[0];
    const float* Wihf = (const float*)d_in[1];
    const float* Whhf = (const float*)d_in[2];
    const float* bihf = (const float*)d_in[3];
    const float* bhhf = (const float*)d_in[4];
    const float* Wihb = (const float*)d_in[5];
    const float* bihb = (const float*)d_in[7];
    const float* bhhb = (const float*)d_in[8];
    const float* W1 = (const float*)d_in[9];   const float* b1 = (const float*)d_in[10];
    const float* W2 = (const float*)d_in[11];  const float* b2 = (const float*)d_in[12];
    const float* W3 = (const float*)d_in[13];  const float* b3 = (const float*)d_in[14];
    float* out = (float*)d_out;

    void* p;
    cudaGetSymbolAddress(&p, g_xp);   float*  xp   = (float*)p;
    cudaGetSymbolAddress(&p, g_last); float*  last = (float*)p;
    cudaGetSymbolAddress(&p, g_gb);   float*  gb   = (float*)p;
    cudaGetSymbolAddress(&p, g_Ah);   __half* Ah   = (__half*)p;
    cudaGetSymbolAddress(&p, g_Wh);   __half* Wh   = (__half*)p;

    const int gemm_smem = 3 * GSTAGE;   // 96 KB
    cudaFuncSetAttribute(gemm_h, cudaFuncAttributeMaxDynamicSharedMemorySize, gemm_smem);

    // lstm at index 3 == the ncu-profiled slot (confirmed R1/R8-R14)
    cvt_fp16<<<(M_FWD * D_) / 1024, 256>>>(x,    Ah, M_FWD * D_);          // 0
    cvt_fp16<<<(G_ * D_) / 1024,    256>>>(Wihf, Wh, G_ * D_);             // 1
    gemm_h<<<dim3(G_ / 128, M_FWD / 128), 256, gemm_smem>>>(Ah, Wh, bihf, bhhf, xp); // 2
    lstm_hmma<<<B_, 512>>>(xp, Whhf, last);                                // 3
    bwd_gemm<<<dim3(4, B_), 1024>>>(x, Wihb, bihb, bhhb, gb);              // 4
    bwd_point<<<B_, 128>>>(gb, last);                                      // 5
    head_kernel<<<B_, 256>>>(last, W1, b1, W2, b2, W3, b3, out);           // 6
}

// round 16
// speedup vs baseline: 1.3647x; 1.0847x over previous
#include <cuda_runtime.h>
#include <cuda_fp16.h>
#include <cstdint>

#define B_  32
#define T_  512
#define D_  2048
#define H_  128
#define G_  512
#define M_FWD (B_ * T_)

typedef unsigned long long ull;

__device__ float  g_xp[M_FWD * G_];       // forward gate preacts [B*T, 4H]
__device__ float  g_last[B_ * 2 * H_];    // [h_fwd | h_bwd]
__device__ float  g_gb[B_ * 384];         // backward gate preacts (i|g|o rows)
__device__ __half g_Ah[M_FWD * D_];       // fp16 copy of inputs
__device__ __half g_Wh[G_ * D_];          // fp16 copy of W_ih_f

extern __shared__ unsigned char dynsmem[];

// ---------------- helpers ---------------------------------------------------
__device__ __forceinline__ uint32_t smem_u32(const void* p) {
    uint32_t a;
    asm("{ .reg .u64 t; cvta.to.shared.u64 t, %1; cvt.u32.u64 %0, t; }"
        : "=r"(a) : "l"(p));
    return a;
}
// precise activations for single-use sites (bwd step, head)
__device__ __forceinline__ float fsig(float x)  { return 1.0f / (1.0f + expf(-x)); }
__device__ __forceinline__ float ftanh(float x) { return tanhf(x); }
// MUFU.TANH activations for the 512-step recurrence: 1 MUFU each (vs EX2+RCP).
// R11 showed the recurrence is strongly contractive to activation error;
// tanh.approx abs err ~1e-4 => predicted output rel_err ~1e-4 (bar: 1e-3).
__device__ __forceinline__ float atanh_(float x) {
    float y; asm("tanh.approx.f32 %0, %1;" : "=f"(y) : "f"(x)); return y;
}
__device__ __forceinline__ float asig_(float x) {
    return fmaf(atanh_(0.5f * x), 0.5f, 0.5f);
}
__device__ __forceinline__ uint32_t h2pack(float2 v) {
    __half2 h = __floats2half2_rn(v.x, v.y);
    return *(uint32_t*)&h;
}

#define SWZ128(o) ((o) ^ (((o) >> 3) & 0x70))

#define LDSM_X4(r0, r1, r2, r3, a) \
    asm volatile("ldmatrix.sync.aligned.m8n8.x4.shared.b16 {%0,%1,%2,%3}, [%4];" \
                 : "=r"(r0), "=r"(r1), "=r"(r2), "=r"(r3) : "r"(a))

#define MMA16816(d, a, b) \
    asm volatile("mma.sync.aligned.m16n8k16.row.col.f32.f16.f16.f32 " \
        "{%0,%1,%2,%3}, {%4,%5,%6,%7}, {%8,%9}, {%0,%1,%2,%3};" \
        : "+f"((d)[0]), "+f"((d)[1]), "+f"((d)[2]), "+f"((d)[3]) \
        : "r"((a)[0]), "r"((a)[1]), "r"((a)[2]), "r"((a)[3]), \
          "r"((b)[0]), "r"((b)[1]))

#define CP_ASYNC16(sa, gp) \
    asm volatile("cp.async.ca.shared.global [%0], [%1], 16;" \
                 :: "r"(sa), "l"(gp) : "memory")
#define CP_COMMIT()  asm volatile("cp.async.commit_group;" ::: "memory")
#define CP_WAIT(n)   asm volatile("cp.async.wait_group %0;" :: "n"(n) : "memory")

// ============================================================================
// fp32 -> fp16 convert
// ============================================================================
__global__ __launch_bounds__(256)
void cvt_fp16(const float* __restrict__ src, __half* __restrict__ dst, int n)
{
    const int i = (blockIdx.x * 256 + threadIdx.x) * 4;
    if (i < n) {
        const float4 v = *(const float4*)(src + i);
        *(__half2*)(dst + i)     = __floats2half2_rn(v.x, v.y);
        *(__half2*)(dst + i + 2) = __floats2half2_rn(v.z, v.w);
    }
}

// ============================================================================
// fp16 GEMM (unchanged: cp.async 3-stage + ldmatrix/mma, ~108 us)
// ============================================================================
#define GSTAGE 32768
#define GNIT   (D_ / 64)    // 32

__global__ __launch_bounds__(256)
void gemm_h(const __half* __restrict__ Ah, const __half* __restrict__ Wh,
            const float* __restrict__ bias0, const float* __restrict__ bias1,
            float* __restrict__ C)
{
    __shared__ float sb[128];
    char* sm = (char*)dynsmem;
    const uint32_t smu = smem_u32(sm);

    const int tid  = threadIdx.x;
    const int wid  = tid >> 5, lane = tid & 31;
    const int wm   = wid & 3,  wn   = wid >> 2;
    const int g    = lane >> 2, tg  = lane & 3;
    const int n0   = blockIdx.x * 128;
    const int m0   = blockIdx.y * 128;

    if (tid < 128) sb[tid] = bias0[n0 + tid] + bias1[n0 + tid];

    const int arow  = wm * 32 + (lane & 15);
    const int acsel = (lane & 16) ? 16 : 0;
    const int brow  = wn * 64 + (lane & 7) + ((lane & 16) ? 8 : 0);
    const int bcsel = (lane & 8) ? 16 : 0;

    const __half* Ab = Ah + (long)m0 * D_;
    const __half* Wb = Wh + (long)n0 * D_;

    const int sr0 = tid >> 3;
    const int sc8 = tid & 7;

    #define ISSUE_STAGE(s, kt) do {                                           \
        const uint32_t _st = smu + (s) * GSTAGE;                              \
        const long _k = (long)(kt) * 64;                                      \
        _Pragma("unroll")                                                     \
        for (int _i = 0; _i < 4; _i++) {                                      \
            const int _r = sr0 + _i * 32;                                     \
            const uint32_t _off = SWZ128(_r * 128 + sc8 * 16);                \
            CP_ASYNC16(_st + _off,         Ab + (long)_r * D_ + _k + sc8 * 8);\
            CP_ASYNC16(_st + 16384 + _off, Wb + (long)_r * D_ + _k + sc8 * 8);\
        }                                                                     \
    } while (0)

    ISSUE_STAGE(0, 0); CP_COMMIT();
    ISSUE_STAGE(1, 1); CP_COMMIT();

    float acc[2][8][4];
    #pragma unroll
    for (int i = 0; i < 2; i++)
        #pragma unroll
        for (int j = 0; j < 8; j++)
            #pragma unroll
            for (int r = 0; r < 4; r++) acc[i][j][r] = 0.0f;

    for (int it = 0; it < GNIT; it++) {
        if (it + 1 < GNIT) CP_WAIT(1); else CP_WAIT(0);
        __syncthreads();
        if (it + 2 < GNIT) { ISSUE_STAGE((it + 2) % 3, it + 2); CP_COMMIT(); }

        const uint32_t a_st = smu + (it % 3) * GSTAGE;
        const uint32_t b_st = a_st + 16384;
        #pragma unroll
        for (int kk = 0; kk < 4; kk++) {
            uint32_t af[2][4], bf[8][2];
            #pragma unroll
            for (int mf = 0; mf < 2; mf++) {
                const uint32_t off =
                    SWZ128((arow + mf * 16) * 128 + kk * 32 + acsel);
                LDSM_X4(af[mf][0], af[mf][1], af[mf][2], af[mf][3], a_st + off);
            }
            #pragma unroll
            for (int np = 0; np < 4; np++) {
                const uint32_t off =
                    SWZ128((brow + np * 16) * 128 + kk * 32 + bcsel);
                uint32_t r0, r1, r2, r3;
                LDSM_X4(r0, r1, r2, r3, b_st + off);
                bf[2 * np][0] = r0;     bf[2 * np][1] = r1;
                bf[2 * np + 1][0] = r2; bf[2 * np + 1][1] = r3;
            }
            #pragma unroll
            for (int mf = 0; mf < 2; mf++)
                #pragma unroll
                for (int nf = 0; nf < 8; nf++)
                    MMA16816(acc[mf][nf], af[mf], bf[nf]);
        }
    }

    #pragma unroll
    for (int mf = 0; mf < 2; mf++) {
        #pragma unroll
        for (int nf = 0; nf < 8; nf++) {
            const int cl  = wn * 64 + nf * 8 + 2 * tg;
            const float b0v = sb[cl], b1v = sb[cl + 1];
            const int r0 = m0 + wm * 32 + mf * 16 + g;
            float2 v0; v0.x = acc[mf][nf][0] + b0v; v0.y = acc[mf][nf][1] + b1v;
            *(float2*)(C + (long)r0 * G_ + n0 + cl) = v0;
            float2 v1; v1.x = acc[mf][nf][2] + b0v; v1.y = acc[mf][nf][3] + b1v;
            *(float2*)(C + (long)(r0 + 8) * G_ + n0 + cl) = v1;
        }
    }
}

// ============================================================================
// Forward LSTM recurrence v11 — R15 gate-fused HMMA structure (one barrier,
// in-lane pointwise) with MUFU.TANH activations: per-thread MUFU ops 10 -> 5,
// halving the MUFU-pipe occupancy spike (~320 -> ~160 cyc/step) that R15
// identified as the reason its barrier/tail removal was a wash.
// ============================================================================
__global__ __launch_bounds__(512)
void lstm_hmma(const float* __restrict__ xp, const float* __restrict__ Whh,
               float* __restrict__ last)
{
    __shared__ __align__(16) __half h16[2][128];

    const int tid = threadIdx.x, b = blockIdx.x;
    const int wid = tid >> 5, lane = tid & 31;
    const int g   = lane >> 2, tg = lane & 3;
    const int j   = wid * 8 + g;          // h-index owned by this lane

    const int ri = j, rf = 128 + j, rg = 256 + j, ro = 384 + j;

    // ---- preload permuted W_hh a-fragments (once; fp32->fp16 on load) ----
    uint32_t af[2][8][4];
    #pragma unroll
    for (int ks = 0; ks < 8; ks++) {
        const float* pi = Whh + ri * 128 + 16 * ks + 2 * tg;
        const float* pf = Whh + rf * 128 + 16 * ks + 2 * tg;
        const float* pg = Whh + rg * 128 + 16 * ks + 2 * tg;
        const float* po = Whh + ro * 128 + 16 * ks + 2 * tg;
        af[0][ks][0] = h2pack(*(const float2*)pi);
        af[0][ks][1] = h2pack(*(const float2*)pf);
        af[0][ks][2] = h2pack(*(const float2*)(pi + 8));
        af[0][ks][3] = h2pack(*(const float2*)(pf + 8));
        af[1][ks][0] = h2pack(*(const float2*)pg);
        af[1][ks][1] = h2pack(*(const float2*)po);
        af[1][ks][2] = h2pack(*(const float2*)(pg + 8));
        af[1][ks][3] = h2pack(*(const float2*)(po + 8));
    }
    if (tid < 128) {
        h16[0][tid] = __float2half_rn(0.0f);
        h16[1][tid] = __float2half_rn(0.0f);
    }
    // permuted write position for h-row j (same permutation as the reader)
    int pos;
    {
        const int r = j & 15;
        pos = (j & ~15) + ((r < 8) ? ((r >> 1) * 4 + (r & 1))
                                   : (((r - 8) >> 1) * 4 + 2 + (r & 1)));
    }
    float c = 0.0f;
    __syncthreads();

    const float* xpb = xp + (long)b * T_ * G_;
    float xi = xpb[ri], xf = xpb[rf], xg = xpb[rg], xo = xpb[ro];

    for (int t = 0; t < T_; t++) {
        const char* hrd = (const char*)h16[t & 1] + tg * 8;
        float acc0[4] = { 0.f, 0.f, 0.f, 0.f };
        float acc1[4] = { 0.f, 0.f, 0.f, 0.f };
        #pragma unroll
        for (int ks = 0; ks < 8; ks++) {
            const ull hv = *(const ull*)(hrd + ks * 32);   // one LDS.64
            uint32_t bf[2];
            bf[0] = (uint32_t)hv;           // k = 2tg, 2tg+1
            bf[1] = (uint32_t)(hv >> 32);   // k = 2tg+8, 2tg+9
            MMA16816(acc0, af[0][ks], bf);
            MMA16816(acc1, af[1][ks], bf);
        }
        const float gi = acc0[0] + xi;
        const float gf = acc0[2] + xf;
        const float gg = acc1[0] + xg;
        const float go = acc1[2] + xo;
        if (t + 1 < T_) {                        // prefetch next xp
            const float* nx = xpb + (long)(t + 1) * G_;
            xi = nx[ri]; xf = nx[rf]; xg = nx[rg]; xo = nx[ro];
        }
        // in-lane pointwise, MUFU.TANH (5 MUFU/thread instead of 10)
        c = asig_(gf) * c + asig_(gi) * atanh_(gg);
        const float h = asig_(go) * atanh_(c);
        if (tg == 0) {
            h16[(t + 1) & 1][pos] = __float2half_rn(h);
            if (t == T_ - 1) last[b * (2 * H_) + j] = h;
        }
        __syncthreads();                          // write(t) -> read(t+1)
    }
}

// ============================================================================
// Backward direction (unchanged): one step from zero state, 128 CTAs.
// ============================================================================
__global__ __launch_bounds__(1024)
void bwd_gemm(const float* __restrict__ x, const float* __restrict__ Wihb,
              const float* __restrict__ bihb, const float* __restrict__ bhhb,
              float* __restrict__ gb)
{
    __shared__ float xs[2048];
    const int b = blockIdx.y, slice = blockIdx.x;
    const int tid = threadIdx.x, warp = tid >> 5, lane = tid & 31;

    const float* xr = x + ((long)b * T_ + (T_ - 1)) * D_;
    for (int i = tid; i < 2048; i += 1024) xs[i] = xr[i];
    __syncthreads();

    #pragma unroll
    for (int jj = 0; jj < 3; jj++) {
        const int j = slice * 96 + warp * 3 + jj;     // 0..383
        const int r = (j < 128) ? j : (j + 128);      // skip f rows
        const float4* wr = (const float4*)(Wihb + (long)r * D_);
        float s = 0.0f;
        #pragma unroll
        for (int it = 0; it < 16; it++) {
            const float4 wv = wr[it * 32 + lane];
            const float4 hx = *(const float4*)(xs + 4 * (it * 32 + lane));
            s += wv.x * hx.x + wv.y * hx.y + wv.z * hx.z + wv.w * hx.w;
        }
        #pragma unroll
        for (int d = 16; d > 0; d >>= 1)
            s += __shfl_xor_sync(0xFFFFFFFFu, s, d);
        if (lane == 0) gb[b * 384 + j] = s + bihb[r] + bhhb[r];
    }
}

__global__ void bwd_point(const float* __restrict__ gb, float* __restrict__ last)
{
    const int b = blockIdx.x, j = threadIdx.x;   // 32 x 128
    const float* r = gb + b * 384;
    const float ci = fsig(r[j]) * ftanh(r[128 + j]);
    last[b * (2 * H_) + H_ + j] = fsig(r[256 + j]) * ftanh(ci);
}

// ============================================================================
// MLP head + softmax.
// ============================================================================
__global__ void head_kernel(const float* __restrict__ last,
                            const float* __restrict__ W1, const float* __restrict__ b1,
                            const float* __restrict__ W2, const float* __restrict__ b2,
                            const float* __restrict__ W3, const float* __restrict__ b3,
                            float* __restrict__ out)
{
    __shared__ float v[256], u[256], w2s[64], lg[11];
    const int b = blockIdx.x, tid = threadIdx.x;

    v[tid] = last[b * 256 + tid];
    __syncthreads();

    float a = b1[tid];
    #pragma unroll 8
    for (int k = 0; k < 256; k++) a = fmaf(W1[tid * 256 + k], v[k], a);
    u[tid] = a;
    __syncthreads();

    if (tid < 64) {
        float s = b2[tid];
        #pragma unroll 8
        for (int k = 0; k < 256; k++) s = fmaf(W2[tid * 256 + k], u[k], s);
        w2s[tid] = s;
    }
    __syncthreads();

    if (tid < 11) {
        float s = b3[tid];
        #pragma unroll
        for (int k = 0; k < 64; k++) s = fmaf(W3[tid * 64 + k], w2s[k], s);
        lg[tid] = s;
    }
    __syncthreads();

    if (tid == 0) {
        float mx = lg[0];
        for (int i = 1; i < 11; i++) mx = fmaxf(mx, lg[i]);
        float e[11], sum = 0.0f;
        for (int i = 0; i < 11; i++) { e[i] = expf(lg[i] - mx); sum += e[i]; }
        const float inv = 1.0f / sum;
        for (int i = 0; i < 11; i++) out[b * 11 + i] = e[i] * inv;
    }
}

// ============================================================================
extern "C" void kernel_launch(void* const* d_in, const int* in_sizes, int n_in,
                              void* d_out, int out_size)
{
    const float* x    = (const float*)d_in[0];
    const float* Wihf = (const float*)d_in[1];
    const float* Whhf = (const float*)d_in[2];
    const float* bihf = (const float*)d_in[3];
    const float* bhhf = (const float*)d_in[4];
    const float* Wihb = (const float*)d_in[5];
    const float* bihb = (const float*)d_in[7];
    const float* bhhb = (const float*)d_in[8];
    const float* W1 = (const float*)d_in[9];   const float* b1 = (const float*)d_in[10];
    const float* W2 = (const float*)d_in[11];  const float* b2 = (const float*)d_in[12];
    const float* W3 = (const float*)d_in[13];  const float* b3 = (const float*)d_in[14];
    float* out = (float*)d_out;

    void* p;
    cudaGetSymbolAddress(&p, g_xp);   float*  xp   = (float*)p;
    cudaGetSymbolAddress(&p, g_last); float*  last = (float*)p;
    cudaGetSymbolAddress(&p, g_gb);   float*  gb   = (float*)p;
    cudaGetSymbolAddress(&p, g_Ah);   __half* Ah   = (__half*)p;
    cudaGetSymbolAddress(&p, g_Wh);   __half* Wh   = (__half*)p;

    const int gemm_smem = 3 * GSTAGE;   // 96 KB
    cudaFuncSetAttribute(gemm_h, cudaFuncAttributeMaxDynamicSharedMemorySize, gemm_smem);

    // lstm at index 3 == the ncu-profiled slot (confirmed R1/R8-R15)
    cvt_fp16<<<(M_FWD * D_) / 1024, 256>>>(x,    Ah, M_FWD * D_);          // 0
    cvt_fp16<<<(G_ * D_) / 1024,    256>>>(Wihf, Wh, G_ * D_);             // 1
    gemm_h<<<dim3(G_ / 128, M_FWD / 128), 256, gemm_smem>>>(Ah, Wh, bihf, bhhf, xp); // 2
    lstm_hmma<<<B_, 512>>>(xp, Whhf, last);                                // 3
    bwd_gemm<<<dim3(4, B_), 1024>>>(x, Wihb, bihb, bhhb, gb);              // 4
    bwd_point<<<B_, 128>>>(gb, last);                                      // 5
    head_kernel<<<B_, 256>>>(last, W1, b1, W2, b2, W3, b3, out);           // 6
}

// round 17
// speedup vs baseline: 1.4045x; 1.0292x over previous
#include <cuda_runtime.h>
#include <cuda_fp16.h>
#include <cstdint>

#define B_  32
#define T_  512
#define D_  2048
#define H_  128
#define G_  512
#define M_FWD (B_ * T_)

typedef unsigned long long ull;

__device__ float  g_xp[M_FWD * G_];       // forward gate preacts [B*T, 4H]
__device__ float  g_last[B_ * 2 * H_];    // [h_fwd | h_bwd]
__device__ float  g_gb[B_ * 384];         // backward gate preacts (i|g|o rows)
__device__ __half g_Wh[G_ * D_];          // fp16 copy of W_ih_f

extern __shared__ unsigned char dynsmem[];

// ---------------- helpers ---------------------------------------------------
__device__ __forceinline__ uint32_t smem_u32(const void* p) {
    uint32_t a;
    asm("{ .reg .u64 t; cvta.to.shared.u64 t, %1; cvt.u32.u64 %0, t; }"
        : "=r"(a) : "l"(p));
    return a;
}
// precise activations for single-use sites (bwd step, head)
__device__ __forceinline__ float fsig(float x)  { return 1.0f / (1.0f + expf(-x)); }
__device__ __forceinline__ float ftanh(float x) { return tanhf(x); }
// MUFU.TANH activations for the recurrence (validated R16: rel_err unmoved)
__device__ __forceinline__ float atanh_(float x) {
    float y; asm("tanh.approx.f32 %0, %1;" : "=f"(y) : "f"(x)); return y;
}
__device__ __forceinline__ float asig_(float x) {
    return fmaf(atanh_(0.5f * x), 0.5f, 0.5f);
}
__device__ __forceinline__ uint32_t h2pack(float2 v) {
    __half2 h = __floats2half2_rn(v.x, v.y);
    return *(uint32_t*)&h;
}

#define SWZ128(o) ((o) ^ (((o) >> 3) & 0x70))

#define LDSM_X4(r0, r1, r2, r3, a) \
    asm volatile("ldmatrix.sync.aligned.m8n8.x4.shared.b16 {%0,%1,%2,%3}, [%4];" \
                 : "=r"(r0), "=r"(r1), "=r"(r2), "=r"(r3) : "r"(a))

#define MMA16816(d, a, b) \
    asm volatile("mma.sync.aligned.m16n8k16.row.col.f32.f16.f16.f32 " \
        "{%0,%1,%2,%3}, {%4,%5,%6,%7}, {%8,%9}, {%0,%1,%2,%3};" \
        : "+f"((d)[0]), "+f"((d)[1]), "+f"((d)[2]), "+f"((d)[3]) \
        : "r"((a)[0]), "r"((a)[1]), "r"((a)[2]), "r"((a)[3]), \
          "r"((b)[0]), "r"((b)[1]))

#define CP_ASYNC16(sa, gp) \
    asm volatile("cp.async.ca.shared.global [%0], [%1], 16;" \
                 :: "r"(sa), "l"(gp) : "memory")
#define CP_COMMIT()  asm volatile("cp.async.commit_group;" ::: "memory")
#define CP_WAIT(n)   asm volatile("cp.async.wait_group %0;" :: "n"(n) : "memory")

// ============================================================================
// fp32 -> fp16 convert (W_ih only now; 4 MB, ~2 us)
// ============================================================================
__global__ __launch_bounds__(256)
void cvt_fp16(const float* __restrict__ src, __half* __restrict__ dst, int n)
{
    const int i = (blockIdx.x * 256 + threadIdx.x) * 4;
    if (i < n) {
        const float4 v = *(const float4*)(src + i);
        *(__half2*)(dst + i)     = __floats2half2_rn(v.x, v.y);
        *(__half2*)(dst + i + 2) = __floats2half2_rn(v.z, v.w);
    }
}

// ============================================================================
// fp16 GEMM v3: C[16384 x 512] = cvt16(A_f32) @ Wh^T + bias0 + bias1
// x-conversion FUSED: A loaded as fp32 (LDG.128), converted to fp16 in regs
// (identical __floats2half2_rn rounding => bit-identical xp), STS to the same
// SW128 layout. A double-buffered via registers (R8 pattern); W keeps the
// proven 3-stage cp.async pipeline. Compute core unchanged.
// smem: A bufs 2 x 16KB @ 0/16384; W stages 3 x 16KB @ 32768+
// ============================================================================
#define GNIT   (D_ / 64)    // 32
#define GSMEM  (2 * 16384 + 3 * 16384)   // 80 KB

__global__ __launch_bounds__(256)
void gemm_hx(const float* __restrict__ A, const __half* __restrict__ Wh,
             const float* __restrict__ bias0, const float* __restrict__ bias1,
             float* __restrict__ C)
{
    __shared__ float sb[128];
    char* sm = (char*)dynsmem;
    const uint32_t smu = smem_u32(sm);

    const int tid  = threadIdx.x;
    const int wid  = tid >> 5, lane = tid & 31;
    const int wm   = wid & 3,  wn   = wid >> 2;
    const int g    = lane >> 2, tg  = lane & 3;
    const int n0   = blockIdx.x * 128;
    const int m0   = blockIdx.y * 128;

    if (tid < 128) sb[tid] = bias0[n0 + tid] + bias1[n0 + tid];

    const int arow  = wm * 32 + (lane & 15);
    const int acsel = (lane & 16) ? 16 : 0;
    const int brow  = wn * 64 + (lane & 7) + ((lane & 16) ? 8 : 0);
    const int bcsel = (lane & 8) ? 16 : 0;

    const float*  Ab = A  + (long)m0 * D_;
    const __half* Wb = Wh + (long)n0 * D_;

    // A staging: 4 chunks/thread; chunk c = tid + i*256 -> row c>>3, 16B c&7
    const int sr0 = tid >> 3;          // rows 0..31 (+32 per i)
    const int sc8 = tid & 7;           // 16B fp16 chunk = 8 halves = 8 floats

    #define LDG_A(kt) do {                                                    \
        const long _k = (long)(kt) * 64 + sc8 * 8;                            \
        _Pragma("unroll")                                                     \
        for (int _i = 0; _i < 4; _i++) {                                      \
            const float* _p = Ab + (long)(sr0 + _i * 32) * D_ + _k;           \
            ra[_i][0] = *(const float4*)_p;                                   \
            ra[_i][1] = *(const float4*)(_p + 4);                             \
        }                                                                     \
    } while (0)

    #define STS_A(buf) do {                                                   \
        char* _pb = sm + (buf) * 16384;                                       \
        _Pragma("unroll")                                                     \
        for (int _i = 0; _i < 4; _i++) {                                      \
            uint4 _v;                                                         \
            _v.x = h2pack(make_float2(ra[_i][0].x, ra[_i][0].y));             \
            _v.y = h2pack(make_float2(ra[_i][0].z, ra[_i][0].w));             \
            _v.z = h2pack(make_float2(ra[_i][1].x, ra[_i][1].y));             \
            _v.w = h2pack(make_float2(ra[_i][1].z, ra[_i][1].w));             \
            *(uint4*)(_pb + SWZ128((sr0 + _i * 32) * 128 + sc8 * 16)) = _v;   \
        }                                                                     \
    } while (0)

    #define ISSUE_W(s, kt) do {                                               \
        const uint32_t _st = smu + 32768 + (s) * 16384;                       \
        const long _k = (long)(kt) * 64;                                      \
        _Pragma("unroll")                                                     \
        for (int _i = 0; _i < 4; _i++) {                                      \
            const int _r = sr0 + _i * 32;                                     \
            CP_ASYNC16(_st + SWZ128(_r * 128 + sc8 * 16),                     \
                       Wb + (long)_r * D_ + _k + sc8 * 8);                    \
        }                                                                     \
    } while (0)

    float4 ra[4][2];

    // ---- prologue ----
    ISSUE_W(0, 0); CP_COMMIT();
    ISSUE_W(1, 1); CP_COMMIT();
    LDG_A(0); STS_A(0);
    LDG_A(1);                      // tile 1 stays in regs through iter 0
    __syncthreads();

    float acc[2][8][4];
    #pragma unroll
    for (int i = 0; i < 2; i++)
        #pragma unroll
        for (int j = 0; j < 8; j++)
            #pragma unroll
            for (int r = 0; r < 4; r++) acc[i][j][r] = 0.0f;

    for (int it = 0; it < GNIT; it++) {
        if (it + 1 < GNIT) CP_WAIT(1); else CP_WAIT(0);
        __syncthreads();
        if (it + 2 < GNIT) { ISSUE_W((it + 2) % 3, it + 2); CP_COMMIT(); }

        const uint32_t a_st = smu + (it & 1) * 16384;
        const uint32_t b_st = smu + 32768 + (it % 3) * 16384;
        #pragma unroll
        for (int kk = 0; kk < 4; kk++) {
            uint32_t af[2][4], bf[8][2];
            #pragma unroll
            for (int mf = 0; mf < 2; mf++) {
                const uint32_t off =
                    SWZ128((arow + mf * 16) * 128 + kk * 32 + acsel);
                LDSM_X4(af[mf][0], af[mf][1], af[mf][2], af[mf][3], a_st + off);
            }
            #pragma unroll
            for (int np = 0; np < 4; np++) {
                const uint32_t off =
                    SWZ128((brow + np * 16) * 128 + kk * 32 + bcsel);
                uint32_t r0, r1, r2, r3;
                LDSM_X4(r0, r1, r2, r3, b_st + off);
                bf[2 * np][0] = r0;     bf[2 * np][1] = r1;
                bf[2 * np + 1][0] = r2; bf[2 * np + 1][1] = r3;
            }
            #pragma unroll
            for (int mf = 0; mf < 2; mf++)
                #pragma unroll
                for (int nf = 0; nf < 8; nf++)
                    MMA16816(acc[mf][nf], af[mf], bf[nf]);
        }

        // stage A: write tile it+1 (regs) to the other buffer; readers of that
        // buffer (iter it-1) finished before this iter's top barrier; the
        // next iter's top barrier publishes it before its readers.
        if (it + 1 < GNIT) {
            STS_A((it + 1) & 1);
            if (it + 2 < GNIT) LDG_A(it + 2);     // lands during iter it+1
        }
    }

    #pragma unroll
    for (int mf = 0; mf < 2; mf++) {
        #pragma unroll
        for (int nf = 0; nf < 8; nf++) {
            const int cl  = wn * 64 + nf * 8 + 2 * tg;
            const float b0v = sb[cl], b1v = sb[cl + 1];
            const int r0 = m0 + wm * 32 + mf * 16 + g;
            float2 v0; v0.x = acc[mf][nf][0] + b0v; v0.y = acc[mf][nf][1] + b1v;
            *(float2*)(C + (long)r0 * G_ + n0 + cl) = v0;
            float2 v1; v1.x = acc[mf][nf][2] + b0v; v1.y = acc[mf][nf][3] + b1v;
            *(float2*)(C + (long)(r0 + 8) * G_ + n0 + cl) = v1;
        }
    }
}

// ============================================================================
// Forward LSTM recurrence v11 (unchanged from R16: 245 us, gate-fused HMMA,
// one barrier, MUFU.TANH pointwise).
// ============================================================================
__global__ __launch_bounds__(512)
void lstm_hmma(const float* __restrict__ xp, const float* __restrict__ Whh,
               float* __restrict__ last)
{
    __shared__ __align__(16) __half h16[2][128];

    const int tid = threadIdx.x, b = blockIdx.x;
    const int wid = tid >> 5, lane = tid & 31;
    const int g   = lane >> 2, tg = lane & 3;
    const int j   = wid * 8 + g;          // h-index owned by this lane

    const int ri = j, rf = 128 + j, rg = 256 + j, ro = 384 + j;

    uint32_t af[2][8][4];
    #pragma unroll
    for (int ks = 0; ks < 8; ks++) {
        const float* pi = Whh + ri * 128 + 16 * ks + 2 * tg;
        const float* pf = Whh + rf * 128 + 16 * ks + 2 * tg;
        const float* pg = Whh + rg * 128 + 16 * ks + 2 * tg;
        const float* po = Whh + ro * 128 + 16 * ks + 2 * tg;
        af[0][ks][0] = h2pack(*(const float2*)pi);
        af[0][ks][1] = h2pack(*(const float2*)pf);
        af[0][ks][2] = h2pack(*(const float2*)(pi + 8));
        af[0][ks][3] = h2pack(*(const float2*)(pf + 8));
        af[1][ks][0] = h2pack(*(const float2*)pg);
        af[1][ks][1] = h2pack(*(const float2*)po);
        af[1][ks][2] = h2pack(*(const float2*)(pg + 8));
        af[1][ks][3] = h2pack(*(const float2*)(po + 8));
    }
    if (tid < 128) {
        h16[0][tid] = __float2half_rn(0.0f);
        h16[1][tid] = __float2half_rn(0.0f);
    }
    int pos;
    {
        const int r = j & 15;
        pos = (j & ~15) + ((r < 8) ? ((r >> 1) * 4 + (r & 1))
                                   : (((r - 8) >> 1) * 4 + 2 + (r & 1)));
    }
    float c = 0.0f;
    __syncthreads();

    const float* xpb = xp + (long)b * T_ * G_;
    float xi = xpb[ri], xf = xpb[rf], xg = xpb[rg], xo = xpb[ro];

    for (int t = 0; t < T_; t++) {
        const char* hrd = (const char*)h16[t & 1] + tg * 8;
        float acc0[4] = { 0.f, 0.f, 0.f, 0.f };
        float acc1[4] = { 0.f, 0.f, 0.f, 0.f };
        #pragma unroll
        for (int ks = 0; ks < 8; ks++) {
            const ull hv = *(const ull*)(hrd + ks * 32);   // one LDS.64
            uint32_t bf[2];
            bf[0] = (uint32_t)hv;
            bf[1] = (uint32_t)(hv >> 32);
            MMA16816(acc0, af[0][ks], bf);
            MMA16816(acc1, af[1][ks], bf);
        }
        const float gi = acc0[0] + xi;
        const float gf = acc0[2] + xf;
        const float gg = acc1[0] + xg;
        const float go = acc1[2] + xo;
        if (t + 1 < T_) {
            const float* nx = xpb + (long)(t + 1) * G_;
            xi = nx[ri]; xf = nx[rf]; xg = nx[rg]; xo = nx[ro];
        }
        c = asig_(gf) * c + asig_(gi) * atanh_(gg);
        const float h = asig_(go) * atanh_(c);
        if (tg == 0) {
            h16[(t + 1) & 1][pos] = __float2half_rn(h);
            if (t == T_ - 1) last[b * (2 * H_) + j] = h;
        }
        __syncthreads();
    }
}

// ============================================================================
// Backward direction (unchanged): one step from zero state, 128 CTAs.
// ============================================================================
__global__ __launch_bounds__(1024)
void bwd_gemm(const float* __restrict__ x, const float* __restrict__ Wihb,
              const float* __restrict__ bihb, const float* __restrict__ bhhb,
              float* __restrict__ gb)
{
    __shared__ float xs[2048];
    const int b = blockIdx.y, slice = blockIdx.x;
    const int tid = threadIdx.x, warp = tid >> 5, lane = tid & 31;

    const float* xr = x + ((long)b * T_ + (T_ - 1)) * D_;
    for (int i = tid; i < 2048; i += 1024) xs[i] = xr[i];
    __syncthreads();

    #pragma unroll
    for (int jj = 0; jj < 3; jj++) {
        const int j = slice * 96 + warp * 3 + jj;     // 0..383
        const int r = (j < 128) ? j : (j + 128);      // skip f rows
        const float4* wr = (const float4*)(Wihb + (long)r * D_);
        float s = 0.0f;
        #pragma unroll
        for (int it = 0; it < 16; it++) {
            const float4 wv = wr[it * 32 + lane];
            const float4 hx = *(const float4*)(xs + 4 * (it * 32 + lane));
            s += wv.x * hx.x + wv.y * hx.y + wv.z * hx.z + wv.w * hx.w;
        }
        #pragma unroll
        for (int d = 16; d > 0; d >>= 1)
            s += __shfl_xor_sync(0xFFFFFFFFu, s, d);
        if (lane == 0) gb[b * 384 + j] = s + bihb[r] + bhhb[r];
    }
}

__global__ void bwd_point(const float* __restrict__ gb, float* __restrict__ last)
{
    const int b = blockIdx.x, j = threadIdx.x;   // 32 x 128
    const float* r = gb + b * 384;
    const float ci = fsig(r[j]) * ftanh(r[128 + j]);
    last[b * (2 * H_) + H_ + j] = fsig(r[256 + j]) * ftanh(ci);
}

// ============================================================================
// MLP head + softmax.
// ============================================================================
__global__ void head_kernel(const float* __restrict__ last,
                            const float* __restrict__ W1, const float* __restrict__ b1,
                            const float* __restrict__ W2, const float* __restrict__ b2,
                            const float* __restrict__ W3, const float* __restrict__ b3,
                            float* __restrict__ out)
{
    __shared__ float v[256], u[256], w2s[64], lg[11];
    const int b = blockIdx.x, tid = threadIdx.x;

    v[tid] = last[b * 256 + tid];
    __syncthreads();

    float a = b1[tid];
    #pragma unroll 8
    for (int k = 0; k < 256; k++) a = fmaf(W1[tid * 256 + k], v[k], a);
    u[tid] = a;
    __syncthreads();

    if (tid < 64) {
        float s = b2[tid];
        #pragma unroll 8
        for (int k = 0; k < 256; k++) s = fmaf(W2[tid * 256 + k], u[k], s);
        w2s[tid] = s;
    }
    __syncthreads();

    if (tid < 11) {
        float s = b3[tid];
        #pragma unroll
        for (int k = 0; k < 64; k++) s = fmaf(W3[tid * 64 + k], w2s[k], s);
        lg[tid] = s;
    }
    __syncthreads();

    if (tid == 0) {
        float mx = lg[0];
        for (int i = 1; i < 11; i++) mx = fmaxf(mx, lg[i]);
        float e[11], sum = 0.0f;
        for (int i = 0; i < 11; i++) { e[i] = expf(lg[i] - mx); sum += e[i]; }
        const float inv = 1.0f / sum;
        for (int i = 0; i < 11; i++) out[b * 11 + i] = e[i] * inv;
    }
}

// ============================================================================
extern "C" void kernel_launch(void* const* d_in, const int* in_sizes, int n_in,
                              void* d_out, int out_size)
{
    const float* x    = (const float*)d_in[0];
    const float* Wihf = (const float*)d_in[1];
    const float* Whhf = (const float*)d_in[2];
    const float* bihf = (const float*)d_in[3];
    const float* bhhf = (const float*)d_in[4];
    const float* Wihb = (const float*)d_in[5];
    const float* bihb = (const float*)d_in[7];
    const float* bhhb = (const float*)d_in[8];
    const float* W1 = (const float*)d_in[9];   const float* b1 = (const float*)d_in[10];
    const float* W2 = (const float*)d_in[11];  const float* b2 = (const float*)d_in[12];
    const float* W3 = (const float*)d_in[13];  const float* b3 = (const float*)d_in[14];
    float* out = (float*)d_out;

    void* p;
    cudaGetSymbolAddress(&p, g_xp);   float*  xp   = (float*)p;
    cudaGetSymbolAddress(&p, g_last); float*  last = (float*)p;
    cudaGetSymbolAddress(&p, g_gb);   float*  gb   = (float*)p;
    cudaGetSymbolAddress(&p, g_Wh);   __half* Wh   = (__half*)p;

    cudaFuncSetAttribute(gemm_hx, cudaFuncAttributeMaxDynamicSharedMemorySize, GSMEM);

    // lstm at index 3 == the ncu-profiled slot (confirmed R1/R8-R16)
    cvt_fp16<<<(G_ * D_) / 1024, 256>>>(Wihf, Wh, G_ * D_);                // 0
    gemm_hx<<<dim3(G_ / 128, M_FWD / 128), 256, GSMEM>>>(x, Wh, bihf, bhhf, xp); // 1
    bwd_gemm<<<dim3(4, B_), 1024>>>(x, Wihb, bihb, bhhb, gb);              // 2
    lstm_hmma<<<B_, 512>>>(xp, Whhf, last);                                // 3
    bwd_point<<<B_, 128>>>(gb, last);                                      // 4
    head_kernel<<<B_, 256>>>(last, W1, b1, W2, b2, W3, b3, out);           // 5
}